// round 1
// baseline (speedup 1.0000x reference)
#include <cuda_runtime.h>
#include <cuda_bf16.h>
#include <math.h>

// Problem constants
#define NN 8192
#define KK 64
#define JS 8                 // j-splits
#define JCHUNK (NN / JS)     // 1024 j's per block
#define IBLK 128             // i's per block (= threads per block)
#define NIB (NN / IBLK)      // 64 i-blocks

// -0.5 / bw^2 with bw = 0.5*128/8192 = 0.0078125  ->  exactly -8192
#define NEG_HALF_INV_BW2 (-8192.0f)

// Scratch (no allocations allowed in kernel_launch)
__device__ float g_kpart[JS][NN];   // partial KDE sums per j-split
__device__ float g_mix[NN];         // mixture pdf per i
__device__ float g_a[KK];           // w_k / sqrt(2*pi*var_k)
__device__ float g_c[KK];           // -0.5 / var_k
__device__ float g_mu[KK];          // means

// ---------------------------------------------------------------------------
// Kernel 1: softmax + per-component constants (tiny; single thread)
// ---------------------------------------------------------------------------
__global__ void gmm_prep_kernel(const float* __restrict__ weight_logits,
                                const float* __restrict__ means,
                                const float* __restrict__ log_vars)
{
    if (threadIdx.x != 0 || blockIdx.x != 0) return;
    const float TWO_PI = 6.283185307179586f;

    float m = -INFINITY;
    for (int k = 0; k < KK; ++k) m = fmaxf(m, weight_logits[k]);
    float s = 0.0f;
    float e[KK];
    for (int k = 0; k < KK; ++k) { e[k] = expf(weight_logits[k] - m); s += e[k]; }
    float invs = 1.0f / s;
    for (int k = 0; k < KK; ++k) {
        float w   = e[k] * invs;
        float var = expf(log_vars[k]);
        g_a[k]  = w / sqrtf(TWO_PI * var);
        g_c[k]  = -0.5f / var;
        g_mu[k] = means[k];
    }
}

// ---------------------------------------------------------------------------
// Kernel 2: pairwise KDE partial sums (+ mixture pdf on j-split 0)
// grid: (NIB, JS), block: IBLK threads
// ---------------------------------------------------------------------------
__global__ void __launch_bounds__(IBLK)
gmm_pair_kernel(const float* __restrict__ x)
{
    __shared__ float tile[JCHUNK];

    const int i  = blockIdx.x * IBLK + threadIdx.x;
    const int jy = blockIdx.y;
    const int j0 = jy * JCHUNK;

    // Stage this block's j-chunk into shared memory (coalesced loads)
    #pragma unroll
    for (int t = 0; t < JCHUNK / IBLK; ++t)
        tile[t * IBLK + threadIdx.x] = x[j0 + t * IBLK + threadIdx.x];
    __syncthreads();

    const float xi = x[i];

    // 4 independent accumulators -> FADD chains don't serialize behind lat=4
    float a0 = 0.0f, a1 = 0.0f, a2 = 0.0f, a3 = 0.0f;
    #pragma unroll 4
    for (int j = 0; j < JCHUNK; j += 4) {
        float d0 = xi - tile[j + 0];
        float d1 = xi - tile[j + 1];
        float d2 = xi - tile[j + 2];
        float d3 = xi - tile[j + 3];
        a0 += __expf(NEG_HALF_INV_BW2 * d0 * d0);
        a1 += __expf(NEG_HALF_INV_BW2 * d1 * d1);
        a2 += __expf(NEG_HALF_INV_BW2 * d2 * d2);
        a3 += __expf(NEG_HALF_INV_BW2 * d3 * d3);
    }
    g_kpart[jy][i] = (a0 + a1) + (a2 + a3);

    // Mixture pdf once per i (K=64 exps — negligible)
    if (jy == 0) {
        float mix = 0.0f;
        #pragma unroll 8
        for (int k = 0; k < KK; ++k) {
            float d = xi - g_mu[k];
            mix += g_a[k] * __expf(g_c[k] * d * d);
        }
        g_mix[i] = mix;
    }
}

// ---------------------------------------------------------------------------
// Kernel 3: combine partials, form sum((mix - data)^2). Deterministic.
// ---------------------------------------------------------------------------
__global__ void gmm_reduce_kernel(float* __restrict__ out)
{
    __shared__ float red[256];
    const int tid = threadIdx.x;

    // 1 / (sqrt(2*pi*bw^2) * N) = 1 / (bw * sqrt(2*pi) * N)
    const float invZ = (float)(1.0 / (0.0078125 * 2.5066282746310002 * 8192.0));

    float acc = 0.0f;
    for (int i = tid; i < NN; i += 256) {
        float s = 0.0f;
        #pragma unroll
        for (int p = 0; p < JS; ++p) s += g_kpart[p][i];
        float diff = g_mix[i] - s * invZ;
        acc += diff * diff;
    }
    red[tid] = acc;
    __syncthreads();
    #pragma unroll
    for (int off = 128; off > 0; off >>= 1) {
        if (tid < off) red[tid] += red[tid + off];
        __syncthreads();
    }
    if (tid == 0) out[0] = red[0];
}

// ---------------------------------------------------------------------------
extern "C" void kernel_launch(void* const* d_in, const int* in_sizes, int n_in,
                              void* d_out, int out_size)
{
    const float* x             = (const float*)d_in[0];
    const float* weight_logits = (const float*)d_in[1];
    const float* means         = (const float*)d_in[2];
    const float* log_vars      = (const float*)d_in[3];
    float* out = (float*)d_out;

    gmm_prep_kernel<<<1, 32>>>(weight_logits, means, log_vars);

    dim3 grid(NIB, JS);
    gmm_pair_kernel<<<grid, IBLK>>>(x);

    gmm_reduce_kernel<<<1, 256>>>(out);
}

// round 2
// speedup vs baseline: 1.5319x; 1.5319x over previous
#include <cuda_runtime.h>
#include <cuda_bf16.h>
#include <math.h>

// Problem constants
#define NN 8192
#define KK 64
#define JS 8                 // j-splits
#define JCHUNK (NN / JS)     // 1024 j's per block
#define IBLK 128             // i's per block (= threads per block)
#define NIB (NN / IBLK)      // 64 i-blocks

// -0.5 / bw^2 with bw = 0.5*128/8192 = 0.0078125  ->  exactly -8192
#define NEG_HALF_INV_BW2 (-8192.0f)

// Scratch (no allocations allowed in kernel_launch)
__device__ float g_kpart[JS][NN];   // partial KDE sums per j-split
__device__ float g_mix[NN];         // mixture pdf per i

// ---------------------------------------------------------------------------
// Kernel 1: pairwise KDE partial sums. jy==0 blocks additionally compute the
// GMM constants (block-redundant parallel softmax) and the mixture pdf.
// grid: (NIB, JS), block: IBLK threads
// ---------------------------------------------------------------------------
__global__ void __launch_bounds__(IBLK)
gmm_pair_kernel(const float* __restrict__ x,
                const float* __restrict__ weight_logits,
                const float* __restrict__ means,
                const float* __restrict__ log_vars)
{
    __shared__ float tile[JCHUNK];
    __shared__ float sa[KK];    // w_k / sqrt(2*pi*var_k)
    __shared__ float sc[KK];    // -0.5 / var_k
    __shared__ float smu[KK];
    __shared__ float red[IBLK];

    const int tid = threadIdx.x;
    const int i   = blockIdx.x * IBLK + tid;
    const int jy  = blockIdx.y;
    const int j0  = jy * JCHUNK;

    // Stage this block's j-chunk into shared memory (coalesced loads)
    #pragma unroll
    for (int t = 0; t < JCHUNK / IBLK; ++t)
        tile[t * IBLK + tid] = x[j0 + t * IBLK + tid];

    // jy==0 blocks: parallel softmax + per-component constants (block-uniform branch)
    if (jy == 0) {
        const float TWO_PI = 6.283185307179586f;
        float l = (tid < KK) ? weight_logits[tid] : -INFINITY;

        // block max over the 64 logits
        red[tid] = l;
        __syncthreads();
        #pragma unroll
        for (int off = IBLK / 2; off > 0; off >>= 1) {
            if (tid < off) red[tid] = fmaxf(red[tid], red[tid + off]);
            __syncthreads();
        }
        float mx = red[0];
        __syncthreads();

        float e = (tid < KK) ? expf(l - mx) : 0.0f;
        red[tid] = e;
        __syncthreads();
        #pragma unroll
        for (int off = IBLK / 2; off > 0; off >>= 1) {
            if (tid < off) red[tid] += red[tid + off];
            __syncthreads();
        }
        float invs = 1.0f / red[0];

        if (tid < KK) {
            float w   = e * invs;
            float var = expf(log_vars[tid]);
            sa[tid]  = w * rsqrtf(TWO_PI * var);
            sc[tid]  = -0.5f / var;
            smu[tid] = means[tid];
        }
    }
    __syncthreads();

    const float xi = x[i];
    const float4* t4 = (const float4*)tile;

    // 8 independent accumulators; broadcast LDS.128 tile reads
    float a0 = 0.f, a1 = 0.f, a2 = 0.f, a3 = 0.f;
    float a4 = 0.f, a5 = 0.f, a6 = 0.f, a7 = 0.f;
    #pragma unroll 4
    for (int j = 0; j < JCHUNK; j += 8) {
        float4 v0 = t4[j / 4];
        float4 v1 = t4[j / 4 + 1];
        float d0 = xi - v0.x, d1 = xi - v0.y, d2 = xi - v0.z, d3 = xi - v0.w;
        float d4 = xi - v1.x, d5 = xi - v1.y, d6 = xi - v1.z, d7 = xi - v1.w;
        a0 += __expf(NEG_HALF_INV_BW2 * d0 * d0);
        a1 += __expf(NEG_HALF_INV_BW2 * d1 * d1);
        a2 += __expf(NEG_HALF_INV_BW2 * d2 * d2);
        a3 += __expf(NEG_HALF_INV_BW2 * d3 * d3);
        a4 += __expf(NEG_HALF_INV_BW2 * d4 * d4);
        a5 += __expf(NEG_HALF_INV_BW2 * d5 * d5);
        a6 += __expf(NEG_HALF_INV_BW2 * d6 * d6);
        a7 += __expf(NEG_HALF_INV_BW2 * d7 * d7);
    }
    g_kpart[jy][i] = ((a0 + a1) + (a2 + a3)) + ((a4 + a5) + (a6 + a7));

    // Mixture pdf once per i (K=64 exps — negligible)
    if (jy == 0) {
        float mix = 0.0f;
        #pragma unroll 8
        for (int k = 0; k < KK; ++k) {
            float d = xi - smu[k];
            mix += sa[k] * __expf(sc[k] * d * d);
        }
        g_mix[i] = mix;
    }
}

// ---------------------------------------------------------------------------
// Kernel 2: combine partials, form sum((mix - data)^2). Deterministic.
// ---------------------------------------------------------------------------
#define RTHREADS 1024
__global__ void __launch_bounds__(RTHREADS)
gmm_reduce_kernel(float* __restrict__ out)
{
    __shared__ float red[RTHREADS];
    const int tid = threadIdx.x;

    // 1 / (sqrt(2*pi*bw^2) * N) = 1 / (bw * sqrt(2*pi) * N)
    const float invZ = (float)(1.0 / (0.0078125 * 2.5066282746310002 * 8192.0));

    float acc = 0.0f;
    #pragma unroll
    for (int t = 0; t < NN / RTHREADS; ++t) {
        int i = t * RTHREADS + tid;
        float s = 0.0f;
        #pragma unroll
        for (int p = 0; p < JS; ++p) s += g_kpart[p][i];
        float diff = g_mix[i] - s * invZ;
        acc += diff * diff;
    }
    red[tid] = acc;
    __syncthreads();
    #pragma unroll
    for (int off = RTHREADS / 2; off > 0; off >>= 1) {
        if (tid < off) red[tid] += red[tid + off];
        __syncthreads();
    }
    if (tid == 0) out[0] = red[0];
}

// ---------------------------------------------------------------------------
extern "C" void kernel_launch(void* const* d_in, const int* in_sizes, int n_in,
                              void* d_out, int out_size)
{
    const float* x             = (const float*)d_in[0];
    const float* weight_logits = (const float*)d_in[1];
    const float* means         = (const float*)d_in[2];
    const float* log_vars      = (const float*)d_in[3];
    float* out = (float*)d_out;

    dim3 grid(NIB, JS);
    gmm_pair_kernel<<<grid, IBLK>>>(x, weight_logits, means, log_vars);

    gmm_reduce_kernel<<<1, RTHREADS>>>(out);
}